// round 1
// baseline (speedup 1.0000x reference)
#include <cuda_runtime.h>
#include <cuda_fp16.h>
#include <math.h>
#include <stdint.h>

// Problem constants (fixed by the dataset)
#define TT 8192
#define HH 2048
#define II 4096
#define EE 8
#define NSLOT (TT * 2)           // 16384 token-slots (top-2)
#define MT 128                   // M tile
#define MAXTILES ((NSLOT / MT) + EE)   // 136 worst-case m-tiles
#define KC 32                    // k-chunk (elements)
#define APITCH 40                // smem row pitch in halfs (conflict-free)

// ----------------------------------------------------------------------------
// Scratch (device globals only — no allocations allowed)
// ----------------------------------------------------------------------------
__device__ int   g_counts[EE];
__device__ int   g_cursor[EE];
__device__ int   g_offsets[EE + 1];
__device__ int   g_tok_e[NSLOT];
__device__ float g_tok_w[NSLOT];
__device__ int   g_perm_tok[NSLOT];
__device__ float g_perm_w[NSLOT];
__device__ int   g_slot_of[NSLOT];
__device__ int   g_ntiles;
__device__ int   g_tile_e[MAXTILES];
__device__ int   g_tile_row0[MAXTILES];
__device__ int   g_tile_rows[MAXTILES];
__device__ __half g_act[(size_t)NSLOT * II];    // 128 MB, fp16 activations (permuted)
__device__ float  g_down[(size_t)NSLOT * HH];   // 128 MB, weighted down-proj per slot

// ----------------------------------------------------------------------------
// Small kernels: init, router, scan, scatter, combine
// ----------------------------------------------------------------------------
__global__ void init_kernel() {
    int i = threadIdx.x;
    if (i < EE) { g_counts[i] = 0; g_cursor[i] = 0; }
}

// one warp per token: logits over 8 experts, top-2, renormalized weights
__global__ void router_kernel(const float* __restrict__ hs,
                              const float* __restrict__ rw) {
    int warp = (blockIdx.x * blockDim.x + threadIdx.x) >> 5;
    int lane = threadIdx.x & 31;
    if (warp >= TT) return;
    const float* x = hs + (size_t)warp * HH;
    float acc[EE];
#pragma unroll
    for (int e = 0; e < EE; e++) acc[e] = 0.f;
    for (int h = lane; h < HH; h += 32) {
        float xv = x[h];
#pragma unroll
        for (int e = 0; e < EE; e++) acc[e] += xv * rw[e * HH + h];
    }
#pragma unroll
    for (int e = 0; e < EE; e++) {
#pragma unroll
        for (int o = 16; o > 0; o >>= 1)
            acc[e] += __shfl_xor_sync(0xffffffffu, acc[e], o);
    }
    if (lane == 0) {
        int i0 = 0; float v0 = acc[0];
#pragma unroll
        for (int e = 1; e < EE; e++) if (acc[e] > v0) { v0 = acc[e]; i0 = e; }
        int i1 = -1; float v1 = -1e30f;
#pragma unroll
        for (int e = 0; e < EE; e++) if (e != i0 && acc[e] > v1) { v1 = acc[e]; i1 = e; }
        // softmax -> top2 -> renorm  ==  softmax over the two top logits
        float p1 = __expf(v1 - v0);
        float s = 1.f + p1;
        g_tok_e[warp * 2 + 0] = i0;
        g_tok_e[warp * 2 + 1] = i1;
        g_tok_w[warp * 2 + 0] = 1.f / s;
        g_tok_w[warp * 2 + 1] = p1 / s;
        atomicAdd(&g_counts[i0], 1);
        atomicAdd(&g_counts[i1], 1);
    }
}

// single-thread scan + tile worklist (E=8, trivial)
__global__ void scan_kernel() {
    int off = 0, nt = 0;
    for (int e = 0; e < EE; e++) {
        g_offsets[e] = off;
        int c = g_counts[e];
        for (int r = 0; r < c; r += MT) {
            g_tile_e[nt] = e;
            g_tile_row0[nt] = off + r;
            int rem = c - r;
            g_tile_rows[nt] = rem < MT ? rem : MT;
            nt++;
        }
        off += c;
    }
    g_offsets[EE] = off;
    g_ntiles = nt;
}

__global__ void scatter_kernel() {
    int i = blockIdx.x * blockDim.x + threadIdx.x;
    if (i >= NSLOT) return;
    int e = g_tok_e[i];
    int pos = atomicAdd(&g_cursor[e], 1);
    int slot = g_offsets[e] + pos;
    g_perm_tok[slot] = i >> 1;
    g_perm_w[slot]   = g_tok_w[i];
    g_slot_of[i]     = slot;
}

// out[t] = down[slot0] + down[slot1]  (weights already applied in GEMM2)
__global__ void combine_kernel(float* __restrict__ out) {
    int i = blockIdx.x * blockDim.x + threadIdx.x;  // over T*H/4
    int t = i >> 9;               // H/4 = 512 float4 per row
    int c = (i & 511) * 4;
    int s0 = g_slot_of[t * 2 + 0];
    int s1 = g_slot_of[t * 2 + 1];
    float4 a = *(const float4*)&g_down[(size_t)s0 * HH + c];
    float4 b = *(const float4*)&g_down[(size_t)s1 * HH + c];
    float4 r;
    r.x = a.x + b.x; r.y = a.y + b.y; r.z = a.z + b.z; r.w = a.w + b.w;
    *(float4*)&out[(size_t)t * HH + c] = r;
}

// ----------------------------------------------------------------------------
// mma helper (m16n8k16, fp16 in, fp32 acc)
// ----------------------------------------------------------------------------
__device__ __forceinline__ void mma16816(float* c, const uint32_t* a, const uint32_t* b) {
    asm volatile(
        "mma.sync.aligned.m16n8k16.row.col.f32.f16.f16.f32 "
        "{%0,%1,%2,%3}, {%4,%5,%6,%7}, {%8,%9}, {%0,%1,%2,%3};\n"
        : "+f"(c[0]), "+f"(c[1]), "+f"(c[2]), "+f"(c[3])
        : "r"(a[0]), "r"(a[1]), "r"(a[2]), "r"(a[3]), "r"(b[0]), "r"(b[1]));
}

// ----------------------------------------------------------------------------
// GEMM1: act[slot, I] = SwiGLU( gather(hidden) @ ws[e].T )
// Block tile: 128 rows x 64 output cols (128 interleaved gate/up weight rows).
// B smem row j: even -> gate row (gb + j/2), odd -> up row (I + gb + j/2),
// so each mma thread's adjacent (c0,c1) = (gate, up) for the same output col.
// ----------------------------------------------------------------------------
__global__ void __launch_bounds__(256, 1)
gemm1_kernel(const float* __restrict__ hs, const float* __restrict__ ws) {
    int tile = blockIdx.x;
    if (tile >= g_ntiles) return;
    const int e    = g_tile_e[tile];
    const int row0 = g_tile_row0[tile];
    const int rows = g_tile_rows[tile];
    const int gb   = blockIdx.y * 64;   // output act col base

    __shared__ __half As[2][MT * APITCH];
    __shared__ __half Bs[2][MT * APITCH];
    __shared__ int    s_tok[MT];

    const int tid = threadIdx.x;
    if (tid < MT) {
        int sl = row0 + tid;
        if (sl >= NSLOT) sl = NSLOT - 1;   // clamped (values beyond rows unused)
        s_tok[tid] = g_perm_tok[sl];
    }
    __syncthreads();

    const int rA   = tid >> 3;   // 0..31 (4 rows per thread, stride 32)
    const int segA = tid & 7;    // float4 segment within 32-float chunk

    const float* aptr[4];
    const float* bptr[4];
    const float* wbase = ws + (size_t)e * (2 * (size_t)II) * HH;
#pragma unroll
    for (int q = 0; q < 4; q++) {
        int r = rA + 32 * q;
        aptr[q] = hs + (size_t)s_tok[r] * HH + segA * 4;
        int wsrow = (r & 1) ? (II + gb + (r >> 1)) : (gb + (r >> 1));
        bptr[q] = wbase + (size_t)wsrow * HH + segA * 4;
    }

    float acc[2][8][4];
#pragma unroll
    for (int i = 0; i < 2; i++)
#pragma unroll
        for (int j = 0; j < 8; j++)
#pragma unroll
            for (int k = 0; k < 4; k++) acc[i][j][k] = 0.f;

    const int lane = tid & 31;
    const int warp = tid >> 5;
    const int wm = warp >> 1, wn = warp & 1;
    const int g = lane >> 2, t4 = lane & 3;

    float4 ra[4], rb[4];

    auto ldg_chunk = [&](int k0) {
#pragma unroll
        for (int q = 0; q < 4; q++) {
            ra[q] = __ldg((const float4*)(aptr[q] + k0));
            rb[q] = __ldg((const float4*)(bptr[q] + k0));
        }
    };
    auto sts_chunk = [&](int buf) {
#pragma unroll
        for (int q = 0; q < 4; q++) {
            int r = rA + 32 * q;
            __half2* pa = (__half2*)&As[buf][r * APITCH + segA * 4];
            pa[0] = __floats2half2_rn(ra[q].x, ra[q].y);
            pa[1] = __floats2half2_rn(ra[q].z, ra[q].w);
            __half2* pb = (__half2*)&Bs[buf][r * APITCH + segA * 4];
            pb[0] = __floats2half2_rn(rb[q].x, rb[q].y);
            pb[1] = __floats2half2_rn(rb[q].z, rb[q].w);
        }
    };

    const int NKC = HH / KC;   // 64
    ldg_chunk(0);
    sts_chunk(0);
    __syncthreads();

    for (int kc = 0; kc < NKC; kc++) {
        const int buf = kc & 1;
        if (kc + 1 < NKC) ldg_chunk((kc + 1) * KC);

#pragma unroll
        for (int ks = 0; ks < KC; ks += 16) {
            uint32_t afr[2][4];
#pragma unroll
            for (int mi = 0; mi < 2; mi++) {
                const __half* ab = &As[buf][(wm * 32 + mi * 16 + g) * APITCH + ks + t4 * 2];
                afr[mi][0] = *(const uint32_t*)(ab);
                afr[mi][1] = *(const uint32_t*)(ab + 8 * APITCH);
                afr[mi][2] = *(const uint32_t*)(ab + 8);
                afr[mi][3] = *(const uint32_t*)(ab + 8 * APITCH + 8);
            }
#pragma unroll
            for (int ni = 0; ni < 8; ni++) {
                const __half* bb = &Bs[buf][(wn * 64 + ni * 8 + g) * APITCH + ks + t4 * 2];
                uint32_t bfr[2];
                bfr[0] = *(const uint32_t*)(bb);
                bfr[1] = *(const uint32_t*)(bb + 8);
                mma16816(acc[0][ni], afr[0], bfr);
                mma16816(acc[1][ni], afr[1], bfr);
            }
        }
        if (kc + 1 < NKC) sts_chunk((kc + 1) & 1);
        __syncthreads();
    }

    // epilogue: fused SwiGLU -> fp16 act
#pragma unroll
    for (int mi = 0; mi < 2; mi++) {
#pragma unroll
        for (int ni = 0; ni < 8; ni++) {
            int col = gb + wn * 32 + ni * 4 + t4;
#pragma unroll
            for (int rr = 0; rr < 2; rr++) {
                int m = wm * 32 + mi * 16 + g + rr * 8;
                if (m < rows) {
                    float gate = acc[mi][ni][rr * 2 + 0];
                    float up   = acc[mi][ni][rr * 2 + 1];
                    float v = gate * up / (1.f + __expf(-gate));
                    g_act[(size_t)(row0 + m) * II + col] = __float2half_rn(v);
                }
            }
        }
    }
}

// ----------------------------------------------------------------------------
// GEMM2: g_down[slot, H] = w_slot * ( act[slot, I] @ w2s[e].T )
// Block tile: 128 rows x 128 output cols, K = I = 4096.
// ----------------------------------------------------------------------------
__global__ void __launch_bounds__(256, 1)
gemm2_kernel(const float* __restrict__ w2s) {
    int tile = blockIdx.x;
    if (tile >= g_ntiles) return;
    const int e    = g_tile_e[tile];
    const int row0 = g_tile_row0[tile];
    const int rows = g_tile_rows[tile];
    const int n0   = blockIdx.y * 128;

    __shared__ __half As[2][MT * APITCH];
    __shared__ __half Bs[2][MT * APITCH];
    __shared__ float  s_w[MT];

    const int tid = threadIdx.x;
    if (tid < MT) {
        int sl = row0 + tid;
        if (sl >= NSLOT) sl = NSLOT - 1;
        s_w[tid] = g_perm_w[sl];
    }
    __syncthreads();

    // A: fp16 from g_act; 32 halfs per row per chunk = 4 uint4; 2 uint4/thread
    const int rA2  = tid >> 2;   // 0..63 (2 rows/thread, stride 64)
    const int seg2 = tid & 3;
    const __half* aptr[2];
#pragma unroll
    for (int q = 0; q < 2; q++) {
        int r = rA2 + 64 * q;
        int sl = row0 + r;
        if (sl >= NSLOT) sl = NSLOT - 1;
        aptr[q] = g_act + (size_t)sl * II + seg2 * 8;
    }

    // B: fp32 from w2s; 8 float4 per row per chunk; 4 float4/thread
    const int rB   = tid >> 3;   // 0..31
    const int segB = tid & 7;
    const float* bptr[4];
    const float* wb = w2s + (size_t)e * HH * II;
#pragma unroll
    for (int q = 0; q < 4; q++) {
        int j = rB + 32 * q;
        bptr[q] = wb + (size_t)(n0 + j) * II + segB * 4;
    }

    float acc[2][8][4];
#pragma unroll
    for (int i = 0; i < 2; i++)
#pragma unroll
        for (int j = 0; j < 8; j++)
#pragma unroll
            for (int k = 0; k < 4; k++) acc[i][j][k] = 0.f;

    const int lane = tid & 31;
    const int warp = tid >> 5;
    const int wm = warp >> 1, wn = warp & 1;
    const int g = lane >> 2, t4 = lane & 3;

    uint4  ua[2];
    float4 rb[4];

    auto ldg_chunk = [&](int k0) {
#pragma unroll
        for (int q = 0; q < 2; q++)
            ua[q] = __ldg((const uint4*)(aptr[q] + k0));
#pragma unroll
        for (int q = 0; q < 4; q++)
            rb[q] = __ldg((const float4*)(bptr[q] + k0));
    };
    auto sts_chunk = [&](int buf) {
#pragma unroll
        for (int q = 0; q < 2; q++) {
            int r = rA2 + 64 * q;
            *(uint4*)&As[buf][r * APITCH + seg2 * 8] = ua[q];
        }
#pragma unroll
        for (int q = 0; q < 4; q++) {
            int r = rB + 32 * q;
            __half2* pb = (__half2*)&Bs[buf][r * APITCH + segB * 4];
            pb[0] = __floats2half2_rn(rb[q].x, rb[q].y);
            pb[1] = __floats2half2_rn(rb[q].z, rb[q].w);
        }
    };

    const int NKC = II / KC;   // 128
    ldg_chunk(0);
    sts_chunk(0);
    __syncthreads();

    for (int kc = 0; kc < NKC; kc++) {
        const int buf = kc & 1;
        if (kc + 1 < NKC) ldg_chunk((kc + 1) * KC);

#pragma unroll
        for (int ks = 0; ks < KC; ks += 16) {
            uint32_t afr[2][4];
#pragma unroll
            for (int mi = 0; mi < 2; mi++) {
                const __half* ab = &As[buf][(wm * 32 + mi * 16 + g) * APITCH + ks + t4 * 2];
                afr[mi][0] = *(const uint32_t*)(ab);
                afr[mi][1] = *(const uint32_t*)(ab + 8 * APITCH);
                afr[mi][2] = *(const uint32_t*)(ab + 8);
                afr[mi][3] = *(const uint32_t*)(ab + 8 * APITCH + 8);
            }
#pragma unroll
            for (int ni = 0; ni < 8; ni++) {
                const __half* bb = &Bs[buf][(wn * 64 + ni * 8 + g) * APITCH + ks + t4 * 2];
                uint32_t bfr[2];
                bfr[0] = *(const uint32_t*)(bb);
                bfr[1] = *(const uint32_t*)(bb + 8);
                mma16816(acc[0][ni], afr[0], bfr);
                mma16816(acc[1][ni], afr[1], bfr);
            }
        }
        if (kc + 1 < NKC) sts_chunk((kc + 1) & 1);
        __syncthreads();
    }

    // epilogue: scale by routing weight, write per-slot down output
#pragma unroll
    for (int mi = 0; mi < 2; mi++) {
#pragma unroll
        for (int ni = 0; ni < 8; ni++) {
            int col = n0 + wn * 64 + ni * 8 + 2 * t4;
#pragma unroll
            for (int rr = 0; rr < 2; rr++) {
                int m = wm * 32 + mi * 16 + g + rr * 8;
                if (m < rows) {
                    float w = s_w[m];
                    float2 v;
                    v.x = acc[mi][ni][rr * 2 + 0] * w;
                    v.y = acc[mi][ni][rr * 2 + 1] * w;
                    *(float2*)&g_down[(size_t)(row0 + m) * HH + col] = v;
                }
            }
        }
    }
}

// ----------------------------------------------------------------------------
// kernel_launch — graph-capturable, allocation-free
// Inputs (metadata order): hidden_states[T,H] f32, router_w[E,H] f32,
//                          ws[E,2I,H] f32, w2s[E,H,I] f32. Output [T,H] f32.
// ----------------------------------------------------------------------------
extern "C" void kernel_launch(void* const* d_in, const int* in_sizes, int n_in,
                              void* d_out, int out_size) {
    const float* hs  = (const float*)d_in[0];
    const float* rw  = (const float*)d_in[1];
    const float* ws  = (const float*)d_in[2];
    const float* w2s = (const float*)d_in[3];
    float* out = (float*)d_out;
    (void)in_sizes; (void)n_in; (void)out_size;

    init_kernel<<<1, 32>>>();
    router_kernel<<<TT / 8, 256>>>(hs, rw);      // 8 warps/block, 1 warp/token
    scan_kernel<<<1, 1>>>();
    scatter_kernel<<<NSLOT / 256, 256>>>();

    dim3 g1(MAXTILES, II / 64);                  // 136 x 64
    gemm1_kernel<<<g1, 256>>>(hs, ws);

    dim3 g2(MAXTILES, HH / 128);                 // 136 x 16
    gemm2_kernel<<<g2, 256>>>(w2s);

    combine_kernel<<<(TT * (HH / 4)) / 256, 256>>>(out);
}

// round 2
// speedup vs baseline: 1.2667x; 1.2667x over previous
#include <cuda_runtime.h>
#include <cuda_fp16.h>
#include <math.h>
#include <stdint.h>

// Problem constants
#define TT 8192
#define HH 2048
#define II 4096
#define EE 8
#define NSLOT (TT * 2)
#define MT 128
#define MAXTILES ((NSLOT / MT) + EE)   // 136

// GEMM tiling: block 128(M) x 256(B-rows), warps 2x4, warp tile 64x64
#define KC 64                 // k elements per stage (128B rows fp16)
#define ASTG 16384            // A stage bytes: 128*128
#define BSTG 32768            // B stage bytes: 256*128
#define STG  (ASTG + BSTG)    // 49152
#define NSTAGE 3
#define SMEM_BYTES (NSTAGE * STG)   // 147456

// ----------------------------------------------------------------------------
// Scratch (device globals only)
// ----------------------------------------------------------------------------
__device__ int   g_counts[EE];
__device__ int   g_cursor[EE];
__device__ int   g_offsets[EE + 1];
__device__ int   g_tok_e[NSLOT];
__device__ float g_tok_w[NSLOT];
__device__ int   g_perm_tok[NSLOT];
__device__ float g_perm_w[NSLOT];
__device__ int   g_slot_of[NSLOT];
__device__ int   g_ntiles;
__device__ int   g_tile_e[MAXTILES];
__device__ int   g_tile_row0[MAXTILES];
__device__ int   g_tile_rows[MAXTILES];

__device__ __half g_hs16[(size_t)TT * HH];               // 32 MB
__device__ __half g_ws16[(size_t)EE * 2 * II * HH];      // 256 MB
__device__ __half g_w2s16[(size_t)EE * HH * II];         // 128 MB
__device__ __half g_act[(size_t)NSLOT * II];             // 128 MB
__device__ float  g_down[(size_t)NSLOT * HH];            // 128 MB

// ----------------------------------------------------------------------------
// PTX helpers
// ----------------------------------------------------------------------------
__device__ __forceinline__ void cpasync16(uint32_t dst, const void* src) {
    asm volatile("cp.async.cg.shared.global [%0], [%1], 16;" :: "r"(dst), "l"(src));
}
__device__ __forceinline__ void cp_commit() {
    asm volatile("cp.async.commit_group;");
}
template <int N>
__device__ __forceinline__ void cp_wait() {
    asm volatile("cp.async.wait_group %0;" :: "n"(N));
}
__device__ __forceinline__ void ldsm4(uint32_t& r0, uint32_t& r1, uint32_t& r2,
                                      uint32_t& r3, uint32_t addr) {
    asm volatile("ldmatrix.sync.aligned.m8n8.x4.shared.b16 {%0,%1,%2,%3}, [%4];"
                 : "=r"(r0), "=r"(r1), "=r"(r2), "=r"(r3) : "r"(addr));
}
__device__ __forceinline__ void mma16816(float* c, const uint32_t* a, const uint32_t* b) {
    asm volatile(
        "mma.sync.aligned.m16n8k16.row.col.f32.f16.f16.f32 "
        "{%0,%1,%2,%3}, {%4,%5,%6,%7}, {%8,%9}, {%0,%1,%2,%3};\n"
        : "+f"(c[0]), "+f"(c[1]), "+f"(c[2]), "+f"(c[3])
        : "r"(a[0]), "r"(a[1]), "r"(a[2]), "r"(a[3]), "r"(b[0]), "r"(b[1]));
}

// ----------------------------------------------------------------------------
// fp32 -> fp16 bulk conversion
// ----------------------------------------------------------------------------
__global__ void cvt_f32_f16(const float4* __restrict__ src, uint2* __restrict__ dst,
                            int n4) {
    int i = blockIdx.x * blockDim.x + threadIdx.x;
    if (i >= n4) return;
    float4 v = src[i];
    __half2 h0 = __floats2half2_rn(v.x, v.y);
    __half2 h1 = __floats2half2_rn(v.z, v.w);
    uint2 u;
    u.x = *(const uint32_t*)&h0;
    u.y = *(const uint32_t*)&h1;
    dst[i] = u;
}

// ----------------------------------------------------------------------------
// Routing kernels
// ----------------------------------------------------------------------------
__global__ void init_kernel() {
    int i = threadIdx.x;
    if (i < EE) { g_counts[i] = 0; g_cursor[i] = 0; }
}

__global__ void router_kernel(const float* __restrict__ hs,
                              const float* __restrict__ rw) {
    int warp = (blockIdx.x * blockDim.x + threadIdx.x) >> 5;
    int lane = threadIdx.x & 31;
    if (warp >= TT) return;
    const float* x = hs + (size_t)warp * HH;
    float acc[EE];
#pragma unroll
    for (int e = 0; e < EE; e++) acc[e] = 0.f;
    for (int h = lane; h < HH; h += 32) {
        float xv = x[h];
#pragma unroll
        for (int e = 0; e < EE; e++) acc[e] += xv * rw[e * HH + h];
    }
#pragma unroll
    for (int e = 0; e < EE; e++) {
#pragma unroll
        for (int o = 16; o > 0; o >>= 1)
            acc[e] += __shfl_xor_sync(0xffffffffu, acc[e], o);
    }
    if (lane == 0) {
        int i0 = 0; float v0 = acc[0];
#pragma unroll
        for (int e = 1; e < EE; e++) if (acc[e] > v0) { v0 = acc[e]; i0 = e; }
        int i1 = -1; float v1 = -1e30f;
#pragma unroll
        for (int e = 0; e < EE; e++) if (e != i0 && acc[e] > v1) { v1 = acc[e]; i1 = e; }
        float p1 = __expf(v1 - v0);
        float s = 1.f + p1;
        g_tok_e[warp * 2 + 0] = i0;
        g_tok_e[warp * 2 + 1] = i1;
        g_tok_w[warp * 2 + 0] = 1.f / s;
        g_tok_w[warp * 2 + 1] = p1 / s;
        atomicAdd(&g_counts[i0], 1);
        atomicAdd(&g_counts[i1], 1);
    }
}

__global__ void scan_kernel() {
    int off = 0, nt = 0;
    for (int e = 0; e < EE; e++) {
        g_offsets[e] = off;
        int c = g_counts[e];
        for (int r = 0; r < c; r += MT) {
            g_tile_e[nt] = e;
            g_tile_row0[nt] = off + r;
            int rem = c - r;
            g_tile_rows[nt] = rem < MT ? rem : MT;
            nt++;
        }
        off += c;
    }
    g_offsets[EE] = off;
    g_ntiles = nt;
}

__global__ void scatter_kernel() {
    int i = blockIdx.x * blockDim.x + threadIdx.x;
    if (i >= NSLOT) return;
    int e = g_tok_e[i];
    int pos = atomicAdd(&g_cursor[e], 1);
    int slot = g_offsets[e] + pos;
    g_perm_tok[slot] = i >> 1;
    g_perm_w[slot]   = g_tok_w[i];
    g_slot_of[i]     = slot;
}

__global__ void combine_kernel(float* __restrict__ out) {
    int i = blockIdx.x * blockDim.x + threadIdx.x;
    int t = i >> 9;
    int c = (i & 511) * 4;
    int s0 = g_slot_of[t * 2 + 0];
    int s1 = g_slot_of[t * 2 + 1];
    float4 a = *(const float4*)&g_down[(size_t)s0 * HH + c];
    float4 b = *(const float4*)&g_down[(size_t)s1 * HH + c];
    float4 r;
    r.x = a.x + b.x; r.y = a.y + b.y; r.z = a.z + b.z; r.w = a.w + b.w;
    *(float4*)&out[(size_t)t * HH + c] = r;
}

// ----------------------------------------------------------------------------
// GEMM1: act = SwiGLU( gather(hs16) @ ws16[e].T )
// Block: M=128 slots x 128 out cols (256 interleaved gate/up B-rows), K=HH.
// blockIdx.x = col block (fastest -> L2 A reuse), blockIdx.y = m-tile.
// ----------------------------------------------------------------------------
__global__ void __launch_bounds__(256, 1)
gemm1_kernel(const __half* __restrict__ hs16, const __half* __restrict__ ws16) {
    const int tile = blockIdx.y;
    if (tile >= g_ntiles) return;
    const int e    = g_tile_e[tile];
    const int row0 = g_tile_row0[tile];
    const int rows = g_tile_rows[tile];
    const int bx   = blockIdx.x;        // 0..31 (128 out cols each)

    extern __shared__ __align__(1024) unsigned char smem[];
    const uint32_t smem_u32 = (uint32_t)__cvta_generic_to_shared(smem);
    __shared__ int s_tok[MT];

    const int tid = threadIdx.x;
    if (tid < MT) {
        int sl = row0 + tid;
        if (sl >= NSLOT) sl = NSLOT - 1;
        s_tok[tid] = g_perm_tok[sl];
    }
    __syncthreads();

    // --- cp.async source/dst setup ---
    // A: thread handles row tid>>1, chunks (tid&1)*4 .. +3
    const int arow  = tid >> 1;
    const int acseg = (tid & 1) * 4;
    const __half* agp = hs16 + (size_t)s_tok[arow] * HH + acseg * 8;
    const uint32_t aP = smem_u32 + arow * 128 + ((arow & 7) << 4);
    // B: thread handles interleaved B-row tid, chunks 0..7
    const int brow = tid;
    const int wrow = (brow & 1) ? (II + bx * 128 + (brow >> 1))
                                : (bx * 128 + (brow >> 1));
    const __half* bgp = ws16 + (size_t)e * (2 * (size_t)II) * HH + (size_t)wrow * HH;
    const uint32_t bP = smem_u32 + ASTG + brow * 128 + ((brow & 7) << 4);

    auto load_stage = [&](int kc, int buf) {
        const uint32_t so = buf * STG;
        const __half* ag = agp + kc * KC;
        const __half* bg = bgp + kc * KC;
#pragma unroll
        for (int j = 0; j < 4; j++)
            cpasync16((aP ^ ((acseg + j) << 4)) + so, ag + j * 8);
#pragma unroll
        for (int c = 0; c < 8; c++)
            cpasync16((bP ^ (c << 4)) + so, bg + c * 8);
    };

    // --- ldmatrix fragment pointers ---
    const int lane = tid & 31;
    const int warp = tid >> 5;
    const int wm = warp >> 2, wn = warp & 3;   // 2 x 4
    const int g = lane >> 2, t4 = lane & 3;

    const int rowA = wm * 64 + (lane & 15);
    const uint32_t PAu = (smem_u32 + rowA * 128 + ((rowA & 7) << 4)) ^ ((lane >> 4) << 4);
    const int rowB = wn * 64 + (lane & 15);
    const uint32_t PBu = (smem_u32 + ASTG + rowB * 128 + ((rowB & 7) << 4)) ^ ((lane >> 4) << 4);

    float acc[4][8][4];
#pragma unroll
    for (int i = 0; i < 4; i++)
#pragma unroll
        for (int j = 0; j < 8; j++)
#pragma unroll
            for (int k = 0; k < 4; k++) acc[i][j][k] = 0.f;

    const int NKC = HH / KC;   // 32
    load_stage(0, 0); cp_commit();
    load_stage(1, 1); cp_commit();

    for (int kc = 0; kc < NKC; kc++) {
        cp_wait<1>();
        __syncthreads();
        const int kn = kc + 2;
        if (kn < NKC) load_stage(kn, kn % NSTAGE);
        cp_commit();

        const uint32_t so = (kc % NSTAGE) * STG;
#pragma unroll
        for (int ksi = 0; ksi < 4; ksi++) {
            const uint32_t kx = ksi << 5;   // (ksi*16)<<1
            uint32_t a[4][4];
#pragma unroll
            for (int mi = 0; mi < 4; mi++)
                ldsm4(a[mi][0], a[mi][1], a[mi][2], a[mi][3],
                      (PAu ^ kx) + so + mi * 2048);
            uint32_t b[8][2];
#pragma unroll
            for (int pr = 0; pr < 4; pr++) {
                uint32_t r0, r1, r2, r3;
                ldsm4(r0, r1, r2, r3, (PBu ^ kx) + so + pr * 2048);
                b[2 * pr + 0][0] = r0; b[2 * pr + 0][1] = r2;
                b[2 * pr + 1][0] = r1; b[2 * pr + 1][1] = r3;
            }
#pragma unroll
            for (int ni = 0; ni < 8; ni++)
#pragma unroll
                for (int mi = 0; mi < 4; mi++)
                    mma16816(acc[mi][ni], a[mi], b[ni]);
        }
    }
    __syncthreads();

    // --- epilogue: SwiGLU, stage in smem, coalesced fp16 store ---
    __half* stg = (__half*)smem;
    const int SP = 136;
#pragma unroll
    for (int mi = 0; mi < 4; mi++)
#pragma unroll
        for (int ni = 0; ni < 8; ni++)
#pragma unroll
            for (int rr = 0; rr < 2; rr++) {
                int m = wm * 64 + mi * 16 + g + rr * 8;
                int col = wn * 32 + ni * 4 + t4;
                float gate = acc[mi][ni][rr * 2 + 0];
                float up   = acc[mi][ni][rr * 2 + 1];
                float v = gate * up / (1.f + __expf(-gate));
                stg[m * SP + col] = __float2half_rn(v);
            }
    __syncthreads();
    {
        int r = tid >> 1, hb = tid & 1;
        if (r < rows) {
            const uint4* s = (const uint4*)&stg[r * SP + hb * 64];
            uint4* d = (uint4*)&g_act[(size_t)(row0 + r) * II + bx * 128 + hb * 64];
#pragma unroll
            for (int q = 0; q < 8; q++) d[q] = s[q];
        }
    }
}

// ----------------------------------------------------------------------------
// GEMM2: g_down = w * ( act @ w2s16[e].T ).  Block: 128 x 256, K = II.
// ----------------------------------------------------------------------------
__global__ void __launch_bounds__(256, 1)
gemm2_kernel(const __half* __restrict__ act, const __half* __restrict__ w2s16) {
    const int tile = blockIdx.y;
    if (tile >= g_ntiles) return;
    const int e    = g_tile_e[tile];
    const int row0 = g_tile_row0[tile];
    const int rows = g_tile_rows[tile];
    const int n0   = blockIdx.x * 256;   // 0..7 col blocks

    extern __shared__ __align__(1024) unsigned char smem[];
    const uint32_t smem_u32 = (uint32_t)__cvta_generic_to_shared(smem);
    __shared__ float s_w[MT];

    const int tid = threadIdx.x;
    if (tid < MT) {
        int sl = row0 + tid;
        if (sl >= NSLOT) sl = NSLOT - 1;
        s_w[tid] = g_perm_w[sl];
    }
    __syncthreads();

    const int arow  = tid >> 1;
    const int acseg = (tid & 1) * 4;
    int asl = row0 + arow;
    if (asl >= NSLOT) asl = NSLOT - 1;
    const __half* agp = act + (size_t)asl * II + acseg * 8;
    const uint32_t aP = smem_u32 + arow * 128 + ((arow & 7) << 4);

    const int brow = tid;
    const __half* bgp = w2s16 + (size_t)e * HH * II + (size_t)(n0 + brow) * II;
    const uint32_t bP = smem_u32 + ASTG + brow * 128 + ((brow & 7) << 4);

    auto load_stage = [&](int kc, int buf) {
        const uint32_t so = buf * STG;
        const __half* ag = agp + kc * KC;
        const __half* bg = bgp + kc * KC;
#pragma unroll
        for (int j = 0; j < 4; j++)
            cpasync16((aP ^ ((acseg + j) << 4)) + so, ag + j * 8);
#pragma unroll
        for (int c = 0; c < 8; c++)
            cpasync16((bP ^ (c << 4)) + so, bg + c * 8);
    };

    const int lane = tid & 31;
    const int warp = tid >> 5;
    const int wm = warp >> 2, wn = warp & 3;
    const int g = lane >> 2, t4 = lane & 3;

    const int rowA = wm * 64 + (lane & 15);
    const uint32_t PAu = (smem_u32 + rowA * 128 + ((rowA & 7) << 4)) ^ ((lane >> 4) << 4);
    const int rowB = wn * 64 + (lane & 15);
    const uint32_t PBu = (smem_u32 + ASTG + rowB * 128 + ((rowB & 7) << 4)) ^ ((lane >> 4) << 4);

    float acc[4][8][4];
#pragma unroll
    for (int i = 0; i < 4; i++)
#pragma unroll
        for (int j = 0; j < 8; j++)
#pragma unroll
            for (int k = 0; k < 4; k++) acc[i][j][k] = 0.f;

    const int NKC = II / KC;   // 64
    load_stage(0, 0); cp_commit();
    load_stage(1, 1); cp_commit();

    for (int kc = 0; kc < NKC; kc++) {
        cp_wait<1>();
        __syncthreads();
        const int kn = kc + 2;
        if (kn < NKC) load_stage(kn, kn % NSTAGE);
        cp_commit();

        const uint32_t so = (kc % NSTAGE) * STG;
#pragma unroll
        for (int ksi = 0; ksi < 4; ksi++) {
            const uint32_t kx = ksi << 5;
            uint32_t a[4][4];
#pragma unroll
            for (int mi = 0; mi < 4; mi++)
                ldsm4(a[mi][0], a[mi][1], a[mi][2], a[mi][3],
                      (PAu ^ kx) + so + mi * 2048);
            uint32_t b[8][2];
#pragma unroll
            for (int pr = 0; pr < 4; pr++) {
                uint32_t r0, r1, r2, r3;
                ldsm4(r0, r1, r2, r3, (PBu ^ kx) + so + pr * 2048);
                b[2 * pr + 0][0] = r0; b[2 * pr + 0][1] = r2;
                b[2 * pr + 1][0] = r1; b[2 * pr + 1][1] = r3;
            }
#pragma unroll
            for (int ni = 0; ni < 8; ni++)
#pragma unroll
                for (int mi = 0; mi < 4; mi++)
                    mma16816(acc[mi][ni], a[mi], b[ni]);
        }
    }

    // epilogue: scale by routing weight, float2 stores (32B/quad, coalesced)
#pragma unroll
    for (int mi = 0; mi < 4; mi++)
#pragma unroll
        for (int ni = 0; ni < 8; ni++)
#pragma unroll
            for (int rr = 0; rr < 2; rr++) {
                int m = wm * 64 + mi * 16 + g + rr * 8;
                if (m < rows) {
                    int col = n0 + wn * 64 + ni * 8 + 2 * t4;
                    float w = s_w[m];
                    float2 v;
                    v.x = acc[mi][ni][rr * 2 + 0] * w;
                    v.y = acc[mi][ni][rr * 2 + 1] * w;
                    *(float2*)&g_down[(size_t)(row0 + m) * HH + col] = v;
                }
            }
}

// ----------------------------------------------------------------------------
// kernel_launch
// ----------------------------------------------------------------------------
extern "C" void kernel_launch(void* const* d_in, const int* in_sizes, int n_in,
                              void* d_out, int out_size) {
    const float* hs  = (const float*)d_in[0];
    const float* rw  = (const float*)d_in[1];
    const float* ws  = (const float*)d_in[2];
    const float* w2s = (const float*)d_in[3];
    float* out = (float*)d_out;
    (void)in_sizes; (void)n_in; (void)out_size;

    static int attr_done = 0;
    if (!attr_done) {
        cudaFuncSetAttribute(gemm1_kernel,
                             cudaFuncAttributeMaxDynamicSharedMemorySize, SMEM_BYTES);
        cudaFuncSetAttribute(gemm2_kernel,
                             cudaFuncAttributeMaxDynamicSharedMemorySize, SMEM_BYTES);
        attr_done = 1;
    }

    __half* hs16  = nullptr; cudaGetSymbolAddress((void**)&hs16,  g_hs16);
    __half* ws16  = nullptr; cudaGetSymbolAddress((void**)&ws16,  g_ws16);
    __half* w2s16 = nullptr; cudaGetSymbolAddress((void**)&w2s16, g_w2s16);
    __half* act   = nullptr; cudaGetSymbolAddress((void**)&act,   g_act);

    // fp32 -> fp16 conversions
    {
        int n4 = (TT * HH) / 4;
        cvt_f32_f16<<<(n4 + 255) / 256, 256>>>((const float4*)hs, (uint2*)hs16, n4);
    }
    {
        int n4 = (EE * 2 * II * HH) / 4;
        cvt_f32_f16<<<(n4 + 255) / 256, 256>>>((const float4*)ws, (uint2*)ws16, n4);
    }
    {
        int n4 = (EE * HH * II) / 4;
        cvt_f32_f16<<<(n4 + 255) / 256, 256>>>((const float4*)w2s, (uint2*)w2s16, n4);
    }

    init_kernel<<<1, 32>>>();
    router_kernel<<<TT / 8, 256>>>(hs, rw);
    scan_kernel<<<1, 1>>>();
    scatter_kernel<<<NSLOT / 256, 256>>>();

    dim3 g1(II / 128, MAXTILES);                 // 32 x 136, col-block fastest
    gemm1_kernel<<<g1, 256, SMEM_BYTES>>>(hs16, ws16);

    dim3 g2(HH / 256, MAXTILES);                 // 8 x 136
    gemm2_kernel<<<g2, 256, SMEM_BYTES>>>(act, w2s16);

    combine_kernel<<<(TT * (HH / 4)) / 256, 256>>>(out);
}